// round 15
// baseline (speedup 1.0000x reference)
#include <cuda_runtime.h>
#include <cuda_bf16.h>
#include <cuda_fp16.h>
#include <cuda_fp8.h>
#include <cstdint>

#define NQ     10000
#define NCAM   6
#define NHEAD  8
#define DH     32
#define DIMS   256
#define SUMHW  5440
#define NLVL   4
#define NPTS   8

// ---------------- scratch (device globals; allocation forbidden) -----------------
__device__ __nv_bfloat16 g_wt_val [256 * 256];   // value_W^T bf16 [N][K]
__device__ __nv_bfloat16 g_wt_q   [768 * 256];   // [off_W ; attw_W]^T bf16
__device__ __nv_bfloat16 g_wt_out [256 * 256];   // out_W^T bf16
__device__ float         g_bias_q [768];         // [off_b ; attw_b]
__device__ float         g_off  [NQ * 512];      // offsets fp32 (with -0.5 folded)
__device__ float         g_attw [NQ * 256];      // raw attn logits
__device__ uint8_t       g_vb8  [NCAM * NHEAD * SUMHW * DH]; // vproj fp8 e4m3 (x16)
__device__ __nv_bfloat16 g_slots_bf[NQ * DIMS];  // pooled features bf16

// ---------------- all weight transposes + bias packing in ONE launch -------------
__global__ __launch_bounds__(256) void wtrans_all_kernel(
    const float* __restrict__ vW, const float* __restrict__ oW,
    const float* __restrict__ aW, const float* __restrict__ uW,
    const float* __restrict__ ob, const float* __restrict__ ab)
{
    const float* W; __nv_bfloat16* D; int N; int roff = 0;
    switch (blockIdx.z) {
        case 0:  W = vW; D = g_wt_val; N = 256; break;
        case 1:  W = oW; D = g_wt_q;   N = 512; break;
        case 2:  W = aW; D = g_wt_q;   N = 256; roff = 512; break;
        default: W = uW; D = g_wt_out; N = 256; break;
    }
    int n0 = blockIdx.x * 32, k0 = blockIdx.y * 32;
    if (n0 >= N) return;
    int t = threadIdx.x;
    if (blockIdx.x == 0 && blockIdx.y == 0) {
        if (blockIdx.z == 1) { g_bias_q[t] = ob[t]; g_bias_q[t + 256] = ob[t + 256]; }
        if (blockIdx.z == 2) { g_bias_q[512 + t] = ab[t]; }
    }
    __shared__ float tile[32][33];
    int tx = t & 31, ty = t >> 5;
#pragma unroll
    for (int i = ty; i < 32; i += 8)
        tile[i][tx] = W[(size_t)(k0 + i) * N + n0 + tx];
    __syncthreads();
#pragma unroll
    for (int i = ty; i < 32; i += 8)
        D[(size_t)(roff + n0 + i) * 256 + k0 + tx] = __float2bfloat16(tile[tx][i]);
}

// ---------------- shared GEMM constants -------------------------------------------
// k-tile = 64 (4 iterations over K=256): doubles compute per load round vs k=32,
// halving exposed load latency (gemm_out was issue=12% dependency-stalled).
#define AST2 72   // smem row stride for 64-k tiles (64 + 8 pad, 16B-aligned)

// ---------------- fused pre-GEMM: 64x128 tiles, k-tile 64 -------------------------
// vproj: blocks [0,1020): row=(bid>>1)*64, col=(bid&1)*128, fp8 epilogue.
// qproj: blocks [1020,1962): row=(tb%157)*64, col=(tb/157)*128, off/attw epilogue.
__global__ __launch_bounds__(256) void gemm_pre_kernel(
    const float* __restrict__ value, const float* __restrict__ query,
    const float* __restrict__ value_b)
{
    __shared__ __nv_bfloat16 Ash[64 * AST2];
    __shared__ __nv_bfloat16 Bsh[128 * AST2];

    const int bid = blockIdx.x;
    const float* A; const __nv_bfloat16* Wt;
    int M, row0, col0, epi;
    if (bid < 1020) {
        A = value; Wt = g_wt_val; M = NCAM * SUMHW;
        row0 = (bid >> 1) * 64; col0 = (bid & 1) * 128; epi = 1;
    } else {
        int tb = bid - 1020;
        A = query; Wt = g_wt_q; M = NQ;
        row0 = (tb % 157) * 64; col0 = (tb / 157) * 128; epi = 2;
    }

    const int t = threadIdx.x;
    const int wid = t >> 5, lane = t & 31;
    const int wm = (wid & 1) * 32;
    const int wn = (wid >> 1) * 32;

    float acc[2][4][4];
#pragma unroll
    for (int a = 0; a < 2; a++)
#pragma unroll
        for (int b = 0; b < 4; b++)
#pragma unroll
            for (int c = 0; c < 4; c++) acc[a][b][c] = 0.f;

    const int a_row = lane & 15;
    const int a_col = (lane >> 4) * 8;
    const int b_row = (lane & 7) + ((lane >> 4) << 3);
    const int b_col = ((lane >> 3) & 1) * 8;

    // staging: A 64 rows x 64 k fp32, 4 thr/row x 16 fp32 each
    const int ra   = t >> 2;
    const int ca   = (t & 3) * 16;
    const int arow = row0 + ra;
    const bool arow_ok = arow < M;
    const float* Abase = A + (size_t)arow * 256 + ca;
    // staging: B 128 rows x 64 k bf16, 2 thr/row x 32 bf16 each
    const int rb   = t >> 1;
    const int cb2  = (t & 1) * 32;
    const __nv_bfloat16* Bbase = Wt + (size_t)(col0 + rb) * 256 + cb2;

    float4 av[4];
    uint4  bv[4];
#pragma unroll
    for (int j = 0; j < 4; j++) av[j] = make_float4(0.f, 0.f, 0.f, 0.f);
    if (arow_ok)
#pragma unroll
        for (int j = 0; j < 4; j++)
            av[j] = *reinterpret_cast<const float4*>(Abase + j * 4);
#pragma unroll
    for (int j = 0; j < 4; j++)
        bv[j] = *reinterpret_cast<const uint4*>(Bbase + j * 8);

    for (int k0 = 0; k0 < 256; k0 += 64) {
        // store staged tiles (A converted fp32 -> bf16)
#pragma unroll
        for (int j = 0; j < 2; j++) {
            __nv_bfloat162 c0 = __floats2bfloat162_rn(av[2*j].x, av[2*j].y);
            __nv_bfloat162 c1 = __floats2bfloat162_rn(av[2*j].z, av[2*j].w);
            __nv_bfloat162 c2 = __floats2bfloat162_rn(av[2*j+1].x, av[2*j+1].y);
            __nv_bfloat162 c3 = __floats2bfloat162_rn(av[2*j+1].z, av[2*j+1].w);
            uint4 st;
            st.x = *reinterpret_cast<uint32_t*>(&c0);
            st.y = *reinterpret_cast<uint32_t*>(&c1);
            st.z = *reinterpret_cast<uint32_t*>(&c2);
            st.w = *reinterpret_cast<uint32_t*>(&c3);
            *reinterpret_cast<uint4*>(Ash + ra * AST2 + ca + j * 8) = st;
        }
#pragma unroll
        for (int j = 0; j < 4; j++)
            *reinterpret_cast<uint4*>(Bsh + rb * AST2 + cb2 + j * 8) = bv[j];
        __syncthreads();
        // prefetch next 64-k tile
        if (k0 < 192) {
            if (arow_ok)
#pragma unroll
                for (int j = 0; j < 4; j++)
                    av[j] = *reinterpret_cast<const float4*>(Abase + k0 + 64 + j * 4);
#pragma unroll
            for (int j = 0; j < 4; j++)
                bv[j] = *reinterpret_cast<const uint4*>(Bbase + k0 + 64 + j * 8);
        }
#pragma unroll
        for (int ks = 0; ks < 4; ks++) {
            uint32_t af[2][4], bfr[2][4];
#pragma unroll
            for (int mi = 0; mi < 2; mi++) {
                uint32_t addr = (uint32_t)__cvta_generic_to_shared(
                    Ash + (wm + mi * 16 + a_row) * AST2 + ks * 16 + a_col);
                asm volatile("ldmatrix.sync.aligned.m8n8.x4.shared.b16 {%0,%1,%2,%3}, [%4];"
                    : "=r"(af[mi][0]), "=r"(af[mi][1]), "=r"(af[mi][2]), "=r"(af[mi][3])
                    : "r"(addr));
            }
#pragma unroll
            for (int bi = 0; bi < 2; bi++) {
                uint32_t addr = (uint32_t)__cvta_generic_to_shared(
                    Bsh + (wn + bi * 16 + b_row) * AST2 + ks * 16 + b_col);
                asm volatile("ldmatrix.sync.aligned.m8n8.x4.shared.b16 {%0,%1,%2,%3}, [%4];"
                    : "=r"(bfr[bi][0]), "=r"(bfr[bi][1]), "=r"(bfr[bi][2]), "=r"(bfr[bi][3])
                    : "r"(addr));
            }
#pragma unroll
            for (int mi = 0; mi < 2; mi++)
#pragma unroll
                for (int ni = 0; ni < 4; ni++) {
                    uint32_t b0 = bfr[ni >> 1][(ni & 1) * 2];
                    uint32_t b1 = bfr[ni >> 1][(ni & 1) * 2 + 1];
                    asm volatile(
                        "mma.sync.aligned.m16n8k16.row.col.f32.bf16.bf16.f32 "
                        "{%0,%1,%2,%3}, {%4,%5,%6,%7}, {%8,%9}, {%0,%1,%2,%3};"
                        : "+f"(acc[mi][ni][0]), "+f"(acc[mi][ni][1]),
                          "+f"(acc[mi][ni][2]), "+f"(acc[mi][ni][3])
                        : "r"(af[mi][0]), "r"(af[mi][1]), "r"(af[mi][2]), "r"(af[mi][3]),
                          "r"(b0), "r"(b1));
                }
        }
        __syncthreads();
    }

    const int lrow = lane >> 2, lcol = (lane & 3) * 2;
#pragma unroll
    for (int mi = 0; mi < 2; mi++)
#pragma unroll
        for (int ni = 0; ni < 4; ni++)
#pragma unroll
            for (int half = 0; half < 2; half++) {
                int grow = row0 + wm + mi * 16 + lrow + half * 8;
                int gcol = col0 + wn + ni * 8 + lcol;
                if (grow >= M) continue;
                float v0 = acc[mi][ni][half * 2 + 0];
                float v1 = acc[mi][ni][half * 2 + 1];
                if (epi == 1) {
                    v0 += value_b[gcol]; v1 += value_b[gcol + 1];
                    int cam = grow / SUMHW, pos = grow - cam * SUMHW;
                    int h = gcol >> 5, ch = gcol & 31;
                    __nv_fp8_storage_t b0 = __nv_cvt_float_to_fp8(
                        v0 * 16.f, __NV_SATFINITE, __NV_E4M3);
                    __nv_fp8_storage_t b1 = __nv_cvt_float_to_fp8(
                        v1 * 16.f, __NV_SATFINITE, __NV_E4M3);
                    uint16_t pk = (uint16_t)b0 | ((uint16_t)b1 << 8);
                    *reinterpret_cast<uint16_t*>(
                        g_vb8 + (((size_t)(cam * NHEAD + h) * SUMHW + pos) * DH + ch)) = pk;
                } else {
                    if (gcol < 512) {
                        v0 += g_bias_q[gcol] - 0.5f;
                        v1 += g_bias_q[gcol + 1] - 0.5f;
                        *reinterpret_cast<float2*>(g_off + (size_t)grow * 512 + gcol) =
                            make_float2(v0, v1);
                    } else {
                        v0 += g_bias_q[gcol]; v1 += g_bias_q[gcol + 1];
                        *reinterpret_cast<float2*>(g_attw + (size_t)grow * 256 + gcol - 512) =
                            make_float2(v0, v1);
                    }
                }
            }
}

// ---------------- out projection GEMM: 64x128 tiles, k-tile 64, grid (157,2) ------
__global__ __launch_bounds__(256) void gemm_out_kernel(
    const __nv_bfloat16* __restrict__ Abf, const float* __restrict__ bias,
    const float* __restrict__ resid, float* __restrict__ C, int M)
{
    __shared__ __nv_bfloat16 Ash[64 * AST2];
    __shared__ __nv_bfloat16 Bsh[128 * AST2];

    const int t = threadIdx.x;
    const int wid = t >> 5, lane = t & 31;
    const int wm = (wid & 1) * 32;
    const int wn = (wid >> 1) * 32;
    const int row0 = blockIdx.x * 64;
    const int col0 = blockIdx.y * 128;

    float acc[2][4][4];
#pragma unroll
    for (int a = 0; a < 2; a++)
#pragma unroll
        for (int b = 0; b < 4; b++)
#pragma unroll
            for (int c = 0; c < 4; c++) acc[a][b][c] = 0.f;

    const int a_row = lane & 15;
    const int a_col = (lane >> 4) * 8;
    const int b_row = (lane & 7) + ((lane >> 4) << 3);
    const int b_col = ((lane >> 3) & 1) * 8;

    const int ra   = t >> 2;
    const int ca   = (t & 3) * 16;     // bf16 elements
    const int arow = row0 + ra;
    const bool arow_ok = arow < M;
    const __nv_bfloat16* Abase = Abf + (size_t)arow * 256 + ca;
    const int rb   = t >> 1;
    const int cb2  = (t & 1) * 32;
    const __nv_bfloat16* Bbase = g_wt_out + (size_t)(col0 + rb) * 256 + cb2;

    uint4 av[2];
    uint4 bv[4];
    av[0] = av[1] = make_uint4(0u, 0u, 0u, 0u);
    if (arow_ok) {
        av[0] = *reinterpret_cast<const uint4*>(Abase);
        av[1] = *reinterpret_cast<const uint4*>(Abase + 8);
    }
#pragma unroll
    for (int j = 0; j < 4; j++)
        bv[j] = *reinterpret_cast<const uint4*>(Bbase + j * 8);

    for (int k0 = 0; k0 < 256; k0 += 64) {
        *reinterpret_cast<uint4*>(Ash + ra * AST2 + ca)     = av[0];
        *reinterpret_cast<uint4*>(Ash + ra * AST2 + ca + 8) = av[1];
#pragma unroll
        for (int j = 0; j < 4; j++)
            *reinterpret_cast<uint4*>(Bsh + rb * AST2 + cb2 + j * 8) = bv[j];
        __syncthreads();
        if (k0 < 192) {
            if (arow_ok) {
                av[0] = *reinterpret_cast<const uint4*>(Abase + k0 + 64);
                av[1] = *reinterpret_cast<const uint4*>(Abase + k0 + 72);
            }
#pragma unroll
            for (int j = 0; j < 4; j++)
                bv[j] = *reinterpret_cast<const uint4*>(Bbase + k0 + 64 + j * 8);
        }
#pragma unroll
        for (int ks = 0; ks < 4; ks++) {
            uint32_t af[2][4], bfr[2][4];
#pragma unroll
            for (int mi = 0; mi < 2; mi++) {
                uint32_t addr = (uint32_t)__cvta_generic_to_shared(
                    Ash + (wm + mi * 16 + a_row) * AST2 + ks * 16 + a_col);
                asm volatile("ldmatrix.sync.aligned.m8n8.x4.shared.b16 {%0,%1,%2,%3}, [%4];"
                    : "=r"(af[mi][0]), "=r"(af[mi][1]), "=r"(af[mi][2]), "=r"(af[mi][3])
                    : "r"(addr));
            }
#pragma unroll
            for (int bi = 0; bi < 2; bi++) {
                uint32_t addr = (uint32_t)__cvta_generic_to_shared(
                    Bsh + (wn + bi * 16 + b_row) * AST2 + ks * 16 + b_col);
                asm volatile("ldmatrix.sync.aligned.m8n8.x4.shared.b16 {%0,%1,%2,%3}, [%4];"
                    : "=r"(bfr[bi][0]), "=r"(bfr[bi][1]), "=r"(bfr[bi][2]), "=r"(bfr[bi][3])
                    : "r"(addr));
            }
#pragma unroll
            for (int mi = 0; mi < 2; mi++)
#pragma unroll
                for (int ni = 0; ni < 4; ni++) {
                    uint32_t b0 = bfr[ni >> 1][(ni & 1) * 2];
                    uint32_t b1 = bfr[ni >> 1][(ni & 1) * 2 + 1];
                    asm volatile(
                        "mma.sync.aligned.m16n8k16.row.col.f32.bf16.bf16.f32 "
                        "{%0,%1,%2,%3}, {%4,%5,%6,%7}, {%8,%9}, {%0,%1,%2,%3};"
                        : "+f"(acc[mi][ni][0]), "+f"(acc[mi][ni][1]),
                          "+f"(acc[mi][ni][2]), "+f"(acc[mi][ni][3])
                        : "r"(af[mi][0]), "r"(af[mi][1]), "r"(af[mi][2]), "r"(af[mi][3]),
                          "r"(b0), "r"(b1));
                }
        }
        __syncthreads();
    }

    const int lrow = lane >> 2, lcol = (lane & 3) * 2;
#pragma unroll
    for (int mi = 0; mi < 2; mi++)
#pragma unroll
        for (int ni = 0; ni < 4; ni++)
#pragma unroll
            for (int half = 0; half < 2; half++) {
                int grow = row0 + wm + mi * 16 + lrow + half * 8;
                int gcol = col0 + wn + ni * 8 + lcol;
                if (grow >= M) continue;
                float v0 = acc[mi][ni][half * 2 + 0] + bias[gcol]
                         + resid[(size_t)grow * 256 + gcol];
                float v1 = acc[mi][ni][half * 2 + 1] + bias[gcol + 1]
                         + resid[(size_t)grow * 256 + gcol + 1];
                *reinterpret_cast<float2*>(C + (size_t)grow * 256 + gcol) =
                    make_float2(v0, v1);
            }
}

// ---------------- fused softmax + sampling + camera mean --------------------------
// block = q, warp = head. Lane = pL*4 + q4; q4 bit0 = x-corner, bit1 = 16-ch half.
// half2 accumulation across cameras; float-domain clamp; hoisted mask scan.
// 6 blocks/SM (40-reg sweet spot — 7 blocks spills, round-10 evidence).
__global__ __launch_bounds__(256, 6) void sample_fused_kernel(
    const float* __restrict__ ref,     // [cam, 1, nq, 4, 2]
    const int*   __restrict__ mask)    // [cam, 1, nq, 4]
{
    const int q    = blockIdx.x;
    const int t    = threadIdx.x;
    const int h    = t >> 5;
    const int lane = t & 31;
    const int pL   = lane >> 2;        // point 0..7
    const int q4   = lane & 3;
    const float xcf = (float)(q4 & 1); // x-corner as float
    const uint32_t lsub = (uint32_t)((q4 & 1) * 32 + (q4 >> 1) * 16);
    const int dd   = pL & 3;

    // hoisted camera-validity scan (6 independent loads, full MLP)
    unsigned vbits = 0;
#pragma unroll
    for (int c = 0; c < NCAM; c++) {
        int4 m4 = *reinterpret_cast<const int4*>(mask + ((size_t)c * NQ + q) * 4);
        if ((m4.x | m4.y | m4.z | m4.w) != 0) vbits |= 1u << c;
    }
    const int cnt = __popc(vbits);

    // softmax over this head's 32 logits (lane <-> logit lvl*8+pt)
    float aw[NLVL];
    {
        float v = g_attw[(size_t)q * 256 + h * 32 + lane];
        float m = v;
#pragma unroll
        for (int o = 16; o; o >>= 1) m = fmaxf(m, __shfl_xor_sync(0xffffffffu, m, o));
        float e = __expf(v - m);
        float s = e;
#pragma unroll
        for (int o = 16; o; o >>= 1) s += __shfl_xor_sync(0xffffffffu, s, o);
        float sm = e / s;
#pragma unroll
        for (int lvl = 0; lvl < NLVL; lvl++)
            aw[lvl] = __shfl_sync(0xffffffffu, sm, lvl * 8 + pL);
    }

    float ox[NLVL], oy[NLVL];   // -0.5 already folded in by the GEMM epilogue
    {
        const float* offq = g_off + (size_t)q * 512 + h * 64;
#pragma unroll
        for (int lvl = 0; lvl < NLVL; lvl++) {
            float2 o = *reinterpret_cast<const float2*>(offq + lvl * 16 + pL * 2);
            ox[lvl] = o.x; oy[lvl] = o.y;
        }
    }

    const uint32_t hb = (uint32_t)h * (SUMHW * DH);

    __half2 hacc[8];
#pragma unroll
    for (int j = 0; j < 8; j++) hacc[j] = __float2half2_rn(0.f);

    for (int c = 0; c < NCAM; c++) {
        if (!((vbits >> c) & 1u)) continue;
        float2 r2 = *reinterpret_cast<const float2*>(
            ref + ((size_t)c * NQ + q) * 8 + dd * 2);
        const float rx = r2.x, ry = r2.y;
        const uint8_t* vbc = g_vb8 + ((uint32_t)c * (NHEAD * SUMHW * DH) + hb);

#pragma unroll
        for (int lvl = 0; lvl < NLVL; lvl++) {
            const int wdim = 64 >> lvl;
            const uint32_t lbase = (lvl == 0) ? 0u : (lvl == 1) ? 131072u
                                 : (lvl == 2) ? 163840u : 172032u;  // LSTART*32
            const float wf = (float)wdim;
            const float wc = (float)(wdim - 2);
            float x = fmaf(rx, wf, ox[lvl]);
            float y = fmaf(ry, wf, oy[lvl]);
            float bxf = floorf(fminf(fmaxf(x, 0.f), wc));
            float byf = floorf(fminf(fmaxf(y, 0.f), wc));
            float fx  = fmaxf(0.f, 1.f - fabsf(x - (bxf + xcf))) * aw[lvl];
            float gy0 = fmaxf(0.f, 1.f - fabsf(y - byf));
            float gy1 = fmaxf(0.f, 1.f - fabsf(y - (byf + 1.f)));
            __half2 wA = __float2half2_rn(gy0 * fx);
            __half2 wB = __float2half2_rn(gy1 * fx);

            int idx = __float2int_rn(fmaf(byf, wf, bxf));
            uint32_t base = lbase + (uint32_t)idx * 32u + lsub;
            uint4 vA = __ldg(reinterpret_cast<const uint4*>(vbc + base));
            uint4 vB = __ldg(reinterpret_cast<const uint4*>(vbc + base + (uint32_t)wdim * 32u));

#define ACCUM16(WH, RAW)                                                          \
            {                                                                     \
                const uint32_t w32[4] = {(RAW).x, (RAW).y, (RAW).z, (RAW).w};     \
                _Pragma("unroll")                                                 \
                for (int wv = 0; wv < 4; wv++) {                                  \
                    uint16_t plo = (uint16_t)(w32[wv] & 0xFFFFu);                 \
                    uint16_t phi = (uint16_t)(w32[wv] >> 16);                     \
                    __half2_raw hlo = __nv_cvt_fp8x2_to_halfraw2(                 \
                        (__nv_fp8x2_storage_t)plo, __NV_E4M3);                    \
                    __half2_raw hhi = __nv_cvt_fp8x2_to_halfraw2(                 \
                        (__nv_fp8x2_storage_t)phi, __NV_E4M3);                    \
                    hacc[wv * 2 + 0] = __hfma2(WH, *reinterpret_cast<__half2*>(&hlo), hacc[wv * 2 + 0]); \
                    hacc[wv * 2 + 1] = __hfma2(WH, *reinterpret_cast<__half2*>(&hhi), hacc[wv * 2 + 1]); \
                }                                                                 \
            }
            ACCUM16(wA, vA)
            ACCUM16(wB, vB)
#undef ACCUM16
        }
    }

    // reduce over lanes sharing a channel group: bits 0 (x-corner), 2,3,4 (points)
#pragma unroll
    for (int s = 0; s < 4; s++) {
        const int off = (s == 0) ? 1 : (1 << (s + 1));
#pragma unroll
        for (int i = 0; i < 8; i++) {
            uint32_t u = *reinterpret_cast<uint32_t*>(&hacc[i]);
            uint32_t v = __shfl_xor_sync(0xffffffffu, u, off);
            hacc[i] = __hadd2(hacc[i], *reinterpret_cast<__half2*>(&v));
        }
    }

    if ((lane & 29) == 0) {   // lanes 0 and 2: channel halves 0 / 1
        const float inv = 0.0625f / (float)max(cnt, 1);  // undo x16 fp8 scale + mean
        float f[16];
#pragma unroll
        for (int j = 0; j < 8; j++) {
            float2 p = __half22float2(hacc[j]);
            f[2 * j]     = p.x * inv;
            f[2 * j + 1] = p.y * inv;
        }
        uint4 pk0, pk1;
        __nv_bfloat162 b0 = __floats2bfloat162_rn(f[0],  f[1]);
        __nv_bfloat162 b1 = __floats2bfloat162_rn(f[2],  f[3]);
        __nv_bfloat162 b2 = __floats2bfloat162_rn(f[4],  f[5]);
        __nv_bfloat162 b3 = __floats2bfloat162_rn(f[6],  f[7]);
        __nv_bfloat162 b4 = __floats2bfloat162_rn(f[8],  f[9]);
        __nv_bfloat162 b5 = __floats2bfloat162_rn(f[10], f[11]);
        __nv_bfloat162 b6 = __floats2bfloat162_rn(f[12], f[13]);
        __nv_bfloat162 b7 = __floats2bfloat162_rn(f[14], f[15]);
        pk0.x = *reinterpret_cast<uint32_t*>(&b0);
        pk0.y = *reinterpret_cast<uint32_t*>(&b1);
        pk0.z = *reinterpret_cast<uint32_t*>(&b2);
        pk0.w = *reinterpret_cast<uint32_t*>(&b3);
        pk1.x = *reinterpret_cast<uint32_t*>(&b4);
        pk1.y = *reinterpret_cast<uint32_t*>(&b5);
        pk1.z = *reinterpret_cast<uint32_t*>(&b6);
        pk1.w = *reinterpret_cast<uint32_t*>(&b7);
        __nv_bfloat16* dst = g_slots_bf + (size_t)q * DIMS + h * DH + (lane >> 1) * 16;
        *reinterpret_cast<uint4*>(dst)     = pk0;
        *reinterpret_cast<uint4*>(dst + 8) = pk1;
    }
}

// ---------------- launcher --------------------------------------------------------
extern "C" void kernel_launch(void* const* d_in, const int* in_sizes, int n_in,
                              void* d_out, int out_size)
{
    const float* query   = (const float*)d_in[0];
    const float* value   = (const float*)d_in[2];
    const float* refp    = (const float*)d_in[3];
    const int*   mask    = (const int*)  d_in[4];
    const float* value_W = (const float*)d_in[7];
    const float* value_b = (const float*)d_in[8];
    const float* off_W   = (const float*)d_in[9];
    const float* off_b   = (const float*)d_in[10];
    const float* attw_W  = (const float*)d_in[11];
    const float* attw_b  = (const float*)d_in[12];
    const float* out_W   = (const float*)d_in[13];
    const float* out_b   = (const float*)d_in[14];

    __nv_bfloat16* p_slots_bf;
    cudaGetSymbolAddress((void**)&p_slots_bf, g_slots_bf);

    // [0] all weight transposes + bias packing
    wtrans_all_kernel<<<dim3(16, 8, 4), 256>>>(
        value_W, off_W, attw_W, out_W, off_b, attw_b);

    // [1] fused pre-GEMM: vproj (fp8 head-major) + offsets/logits, k-tile 64
    gemm_pre_kernel<<<1962, 256>>>(value, query, value_b);

    // [2] fused softmax + sampling + camera mean
    sample_fused_kernel<<<NQ, 256>>>(refp, mask);

    // [3] output projection + bias + residual (64x128 tiles, k-tile 64)
    gemm_out_kernel<<<dim3(157, 2), 256>>>(p_slots_bf, out_b, query, (float*)d_out, NQ);
}

// round 16
// speedup vs baseline: 1.0736x; 1.0736x over previous
#include <cuda_runtime.h>
#include <cuda_bf16.h>
#include <cuda_fp16.h>
#include <cuda_fp8.h>
#include <cstdint>

#define NQ     10000
#define NCAM   6
#define NHEAD  8
#define DH     32
#define DIMS   256
#define SUMHW  5440
#define NLVL   4
#define NPTS   8

// ---------------- scratch (device globals; allocation forbidden) -----------------
__device__ __nv_bfloat16 g_wt_val [256 * 256];   // value_W^T bf16 [N][K]
__device__ __nv_bfloat16 g_wt_q   [768 * 256];   // [off_W ; attw_W]^T bf16
__device__ __nv_bfloat16 g_wt_out [256 * 256];   // out_W^T bf16
__device__ float         g_bias_q [768];         // [off_b ; attw_b]
__device__ float         g_off  [NQ * 512];      // offsets fp32 (with -0.5 folded)
__device__ float         g_attw [NQ * 256];      // raw attn logits
__device__ uint8_t       g_vb8  [NCAM * NHEAD * SUMHW * DH]; // vproj fp8 e4m3 (x16)
__device__ __nv_bfloat16 g_slots_bf[NQ * DIMS];  // pooled features bf16

// ---------------- all weight transposes + bias packing in ONE launch -------------
__global__ __launch_bounds__(256) void wtrans_all_kernel(
    const float* __restrict__ vW, const float* __restrict__ oW,
    const float* __restrict__ aW, const float* __restrict__ uW,
    const float* __restrict__ ob, const float* __restrict__ ab)
{
    const float* W; __nv_bfloat16* D; int N; int roff = 0;
    switch (blockIdx.z) {
        case 0:  W = vW; D = g_wt_val; N = 256; break;
        case 1:  W = oW; D = g_wt_q;   N = 512; break;
        case 2:  W = aW; D = g_wt_q;   N = 256; roff = 512; break;
        default: W = uW; D = g_wt_out; N = 256; break;
    }
    int n0 = blockIdx.x * 32, k0 = blockIdx.y * 32;
    if (n0 >= N) return;
    int t = threadIdx.x;
    if (blockIdx.x == 0 && blockIdx.y == 0) {
        if (blockIdx.z == 1) { g_bias_q[t] = ob[t]; g_bias_q[t + 256] = ob[t + 256]; }
        if (blockIdx.z == 2) { g_bias_q[512 + t] = ab[t]; }
    }
    __shared__ float tile[32][33];
    int tx = t & 31, ty = t >> 5;
#pragma unroll
    for (int i = ty; i < 32; i += 8)
        tile[i][tx] = W[(size_t)(k0 + i) * N + n0 + tx];
    __syncthreads();
#pragma unroll
    for (int i = ty; i < 32; i += 8)
        D[(size_t)(roff + n0 + i) * 256 + k0 + tx] = __float2bfloat16(tile[tx][i]);
}

// ---------------- shared GEMM constants -------------------------------------------
#define AST 40

// ---------------- fused pre-GEMM: 64x128 tiles, k-tile 32 (R13 best config) -------
// vproj: blocks [0,1020): row=(bid>>1)*64, col=(bid&1)*128, fp8 epilogue.
// qproj: blocks [1020,1962): row=(tb%157)*64, col=(tb/157)*128, off/attw epilogue.
__global__ __launch_bounds__(256) void gemm_pre_kernel(
    const float* __restrict__ value, const float* __restrict__ query,
    const float* __restrict__ value_b)
{
    __shared__ __nv_bfloat16 Ash[64 * AST];
    __shared__ __nv_bfloat16 Bsh[128 * AST];

    const int bid = blockIdx.x;
    const float* A; const __nv_bfloat16* Wt;
    int M, row0, col0, epi;
    if (bid < 1020) {
        A = value; Wt = g_wt_val; M = NCAM * SUMHW;
        row0 = (bid >> 1) * 64; col0 = (bid & 1) * 128; epi = 1;
    } else {
        int tb = bid - 1020;
        A = query; Wt = g_wt_q; M = NQ;
        row0 = (tb % 157) * 64; col0 = (tb / 157) * 128; epi = 2;
    }

    const int t = threadIdx.x;
    const int wid = t >> 5, lane = t & 31;
    const int wm = (wid & 1) * 32;
    const int wn = (wid >> 1) * 32;

    float acc[2][4][4];
#pragma unroll
    for (int a = 0; a < 2; a++)
#pragma unroll
        for (int b = 0; b < 4; b++)
#pragma unroll
            for (int c = 0; c < 4; c++) acc[a][b][c] = 0.f;

    const int a_row = lane & 15;
    const int a_col = (lane >> 4) * 8;
    const int b_row = (lane & 7) + ((lane >> 4) << 3);
    const int b_col = ((lane >> 3) & 1) * 8;

    const int r   = t >> 2;
    const int cfo = (t & 3) * 8;
    const int arow = row0 + r;
    const bool arow_ok = arow < M;
    const float* Abase = A + (size_t)arow * 256 + cfo;
    const __nv_bfloat16* Bbase0 = Wt + (size_t)(col0 + r) * 256 + cfo;

    float4 a0 = make_float4(0.f, 0.f, 0.f, 0.f);
    float4 a1 = a0;
    if (arow_ok) {
        a0 = *reinterpret_cast<const float4*>(Abase);
        a1 = *reinterpret_cast<const float4*>(Abase + 4);
    }
    uint4 breg[2];
#pragma unroll
    for (int j = 0; j < 2; j++)
        breg[j] = *reinterpret_cast<const uint4*>(Bbase0 + (size_t)j * 64 * 256);

    for (int k0 = 0; k0 < 256; k0 += 32) {
        {
            __nv_bfloat162 b0 = __floats2bfloat162_rn(a0.x, a0.y);
            __nv_bfloat162 b1 = __floats2bfloat162_rn(a0.z, a0.w);
            __nv_bfloat162 b2 = __floats2bfloat162_rn(a1.x, a1.y);
            __nv_bfloat162 b3 = __floats2bfloat162_rn(a1.z, a1.w);
            uint4 st;
            st.x = *reinterpret_cast<uint32_t*>(&b0);
            st.y = *reinterpret_cast<uint32_t*>(&b1);
            st.z = *reinterpret_cast<uint32_t*>(&b2);
            st.w = *reinterpret_cast<uint32_t*>(&b3);
            *reinterpret_cast<uint4*>(Ash + r * AST + cfo) = st;
#pragma unroll
            for (int j = 0; j < 2; j++)
                *reinterpret_cast<uint4*>(Bsh + (r + j * 64) * AST + cfo) = breg[j];
        }
        __syncthreads();
        if (k0 < 224) {
            if (arow_ok) {
                a0 = *reinterpret_cast<const float4*>(Abase + k0 + 32);
                a1 = *reinterpret_cast<const float4*>(Abase + k0 + 36);
            }
#pragma unroll
            for (int j = 0; j < 2; j++)
                breg[j] = *reinterpret_cast<const uint4*>(
                    Bbase0 + (size_t)j * 64 * 256 + k0 + 32);
        }
#pragma unroll
        for (int ks = 0; ks < 2; ks++) {
            uint32_t af[2][4], bfr[2][4];
#pragma unroll
            for (int mi = 0; mi < 2; mi++) {
                uint32_t addr = (uint32_t)__cvta_generic_to_shared(
                    Ash + (wm + mi * 16 + a_row) * AST + ks * 16 + a_col);
                asm volatile("ldmatrix.sync.aligned.m8n8.x4.shared.b16 {%0,%1,%2,%3}, [%4];"
                    : "=r"(af[mi][0]), "=r"(af[mi][1]), "=r"(af[mi][2]), "=r"(af[mi][3])
                    : "r"(addr));
            }
#pragma unroll
            for (int bi = 0; bi < 2; bi++) {
                uint32_t addr = (uint32_t)__cvta_generic_to_shared(
                    Bsh + (wn + bi * 16 + b_row) * AST + ks * 16 + b_col);
                asm volatile("ldmatrix.sync.aligned.m8n8.x4.shared.b16 {%0,%1,%2,%3}, [%4];"
                    : "=r"(bfr[bi][0]), "=r"(bfr[bi][1]), "=r"(bfr[bi][2]), "=r"(bfr[bi][3])
                    : "r"(addr));
            }
#pragma unroll
            for (int mi = 0; mi < 2; mi++)
#pragma unroll
                for (int ni = 0; ni < 4; ni++) {
                    uint32_t b0 = bfr[ni >> 1][(ni & 1) * 2];
                    uint32_t b1 = bfr[ni >> 1][(ni & 1) * 2 + 1];
                    asm volatile(
                        "mma.sync.aligned.m16n8k16.row.col.f32.bf16.bf16.f32 "
                        "{%0,%1,%2,%3}, {%4,%5,%6,%7}, {%8,%9}, {%0,%1,%2,%3};"
                        : "+f"(acc[mi][ni][0]), "+f"(acc[mi][ni][1]),
                          "+f"(acc[mi][ni][2]), "+f"(acc[mi][ni][3])
                        : "r"(af[mi][0]), "r"(af[mi][1]), "r"(af[mi][2]), "r"(af[mi][3]),
                          "r"(b0), "r"(b1));
                }
        }
        __syncthreads();
    }

    const int lrow = lane >> 2, lcol = (lane & 3) * 2;
#pragma unroll
    for (int mi = 0; mi < 2; mi++)
#pragma unroll
        for (int ni = 0; ni < 4; ni++)
#pragma unroll
            for (int half = 0; half < 2; half++) {
                int grow = row0 + wm + mi * 16 + lrow + half * 8;
                int gcol = col0 + wn + ni * 8 + lcol;
                if (grow >= M) continue;
                float v0 = acc[mi][ni][half * 2 + 0];
                float v1 = acc[mi][ni][half * 2 + 1];
                if (epi == 1) {
                    v0 += value_b[gcol]; v1 += value_b[gcol + 1];
                    int cam = grow / SUMHW, pos = grow - cam * SUMHW;
                    int h = gcol >> 5, ch = gcol & 31;
                    __nv_fp8_storage_t b0 = __nv_cvt_float_to_fp8(
                        v0 * 16.f, __NV_SATFINITE, __NV_E4M3);
                    __nv_fp8_storage_t b1 = __nv_cvt_float_to_fp8(
                        v1 * 16.f, __NV_SATFINITE, __NV_E4M3);
                    uint16_t pk = (uint16_t)b0 | ((uint16_t)b1 << 8);
                    *reinterpret_cast<uint16_t*>(
                        g_vb8 + (((size_t)(cam * NHEAD + h) * SUMHW + pos) * DH + ch)) = pk;
                } else {
                    if (gcol < 512) {
                        v0 += g_bias_q[gcol] - 0.5f;
                        v1 += g_bias_q[gcol + 1] - 0.5f;
                        *reinterpret_cast<float2*>(g_off + (size_t)grow * 512 + gcol) =
                            make_float2(v0, v1);
                    } else {
                        v0 += g_bias_q[gcol]; v1 += g_bias_q[gcol + 1];
                        *reinterpret_cast<float2*>(g_attw + (size_t)grow * 256 + gcol - 512) =
                            make_float2(v0, v1);
                    }
                }
            }
}

// ---------------- out projection GEMM: 64x64 tiles, grid (157,4), k-tile 32 -------
// R13 config + residual prefetch at kernel start (overlaps epilogue DRAM latency
// with the mainloop; GEMM shape tuning is plateaued per rounds 12-15 evidence).
__global__ __launch_bounds__(256) void gemm_out_kernel(
    const __nv_bfloat16* __restrict__ Abf, const float* __restrict__ bias,
    const float* __restrict__ resid, float* __restrict__ C, int M)
{
    __shared__ __nv_bfloat16 Ash[64 * AST];
    __shared__ __nv_bfloat16 Bsh[64 * AST];

    const int t = threadIdx.x;
    const int wid = t >> 5, lane = t & 31;
    const int wm = (wid & 1) * 32;
    const int wn = (wid >> 1) * 16;
    const int row0 = blockIdx.x * 64;
    const int col0 = blockIdx.y * 64;

    float acc[2][2][4];
#pragma unroll
    for (int a = 0; a < 2; a++)
#pragma unroll
        for (int b = 0; b < 2; b++)
#pragma unroll
            for (int c = 0; c < 4; c++) acc[a][b][c] = 0.f;

    const int a_row = lane & 15;
    const int a_col = (lane >> 4) * 8;
    const int b_row = (lane & 7) + ((lane >> 4) << 3);
    const int b_col = ((lane >> 3) & 1) * 8;

    const int lrow = lane >> 2, lcol = (lane & 3) * 2;

    // prefetch residuals for this thread's 8 output fragments (hides epilogue DRAM)
    float2 rv[2][2][2];
#pragma unroll
    for (int mi = 0; mi < 2; mi++)
#pragma unroll
        for (int ni = 0; ni < 2; ni++)
#pragma unroll
            for (int half = 0; half < 2; half++) {
                int grow = row0 + wm + mi * 16 + lrow + half * 8;
                int gcol = col0 + wn + ni * 8 + lcol;
                rv[mi][ni][half] = (grow < M)
                    ? *reinterpret_cast<const float2*>(resid + (size_t)grow * 256 + gcol)
                    : make_float2(0.f, 0.f);
            }

    const int r   = t >> 2;
    const int cfo = (t & 3) * 8;
    const int arow = row0 + r;
    const bool arow_ok = arow < M;
    const __nv_bfloat16* Abase = Abf + (size_t)arow * 256 + cfo;
    const __nv_bfloat16* Bbase0 = g_wt_out + (size_t)(col0 + r) * 256 + cfo;

    uint4 areg = make_uint4(0u, 0u, 0u, 0u);
    if (arow_ok) areg = *reinterpret_cast<const uint4*>(Abase);
    uint4 breg = *reinterpret_cast<const uint4*>(Bbase0);

    for (int k0 = 0; k0 < 256; k0 += 32) {
        *reinterpret_cast<uint4*>(Ash + r * AST + cfo) = areg;
        *reinterpret_cast<uint4*>(Bsh + r * AST + cfo) = breg;
        __syncthreads();
        if (k0 < 224) {
            if (arow_ok) areg = *reinterpret_cast<const uint4*>(Abase + k0 + 32);
            breg = *reinterpret_cast<const uint4*>(Bbase0 + k0 + 32);
        }
#pragma unroll
        for (int ks = 0; ks < 2; ks++) {
            uint32_t af[2][4], bfr[4];
#pragma unroll
            for (int mi = 0; mi < 2; mi++) {
                uint32_t addr = (uint32_t)__cvta_generic_to_shared(
                    Ash + (wm + mi * 16 + a_row) * AST + ks * 16 + a_col);
                asm volatile("ldmatrix.sync.aligned.m8n8.x4.shared.b16 {%0,%1,%2,%3}, [%4];"
                    : "=r"(af[mi][0]), "=r"(af[mi][1]), "=r"(af[mi][2]), "=r"(af[mi][3])
                    : "r"(addr));
            }
            {
                uint32_t addr = (uint32_t)__cvta_generic_to_shared(
                    Bsh + (wn + b_row) * AST + ks * 16 + b_col);
                asm volatile("ldmatrix.sync.aligned.m8n8.x4.shared.b16 {%0,%1,%2,%3}, [%4];"
                    : "=r"(bfr[0]), "=r"(bfr[1]), "=r"(bfr[2]), "=r"(bfr[3])
                    : "r"(addr));
            }
#pragma unroll
            for (int mi = 0; mi < 2; mi++)
#pragma unroll
                for (int ni = 0; ni < 2; ni++) {
                    asm volatile(
                        "mma.sync.aligned.m16n8k16.row.col.f32.bf16.bf16.f32 "
                        "{%0,%1,%2,%3}, {%4,%5,%6,%7}, {%8,%9}, {%0,%1,%2,%3};"
                        : "+f"(acc[mi][ni][0]), "+f"(acc[mi][ni][1]),
                          "+f"(acc[mi][ni][2]), "+f"(acc[mi][ni][3])
                        : "r"(af[mi][0]), "r"(af[mi][1]), "r"(af[mi][2]), "r"(af[mi][3]),
                          "r"(bfr[ni * 2]), "r"(bfr[ni * 2 + 1]));
                }
        }
        __syncthreads();
    }

#pragma unroll
    for (int mi = 0; mi < 2; mi++)
#pragma unroll
        for (int ni = 0; ni < 2; ni++)
#pragma unroll
            for (int half = 0; half < 2; half++) {
                int grow = row0 + wm + mi * 16 + lrow + half * 8;
                int gcol = col0 + wn + ni * 8 + lcol;
                if (grow >= M) continue;
                float v0 = acc[mi][ni][half * 2 + 0] + bias[gcol]
                         + rv[mi][ni][half].x;
                float v1 = acc[mi][ni][half * 2 + 1] + bias[gcol + 1]
                         + rv[mi][ni][half].y;
                *reinterpret_cast<float2*>(C + (size_t)grow * 256 + gcol) =
                    make_float2(v0, v1);
            }
}

// ---------------- fused softmax + sampling + camera mean --------------------------
// block = q, warp = head. Lane = pL*4 + q4; q4 bit0 = x-corner, bit1 = 16-ch half.
// half2 accumulation across cameras; float-domain clamp; hoisted mask scan;
// camera loop fully unrolled (uniform predication, cross-camera LDG batching).
// 6 blocks/SM (40-reg sweet spot — 7 blocks spills, round-10 evidence).
__global__ __launch_bounds__(256, 6) void sample_fused_kernel(
    const float* __restrict__ ref,     // [cam, 1, nq, 4, 2]
    const int*   __restrict__ mask)    // [cam, 1, nq, 4]
{
    const int q    = blockIdx.x;
    const int t    = threadIdx.x;
    const int h    = t >> 5;
    const int lane = t & 31;
    const int pL   = lane >> 2;        // point 0..7
    const int q4   = lane & 3;
    const float xcf = (float)(q4 & 1); // x-corner as float
    const uint32_t lsub = (uint32_t)((q4 & 1) * 32 + (q4 >> 1) * 16);
    const int dd   = pL & 3;

    // hoisted camera-validity scan (6 independent loads, full MLP)
    unsigned vbits = 0;
#pragma unroll
    for (int c = 0; c < NCAM; c++) {
        int4 m4 = *reinterpret_cast<const int4*>(mask + ((size_t)c * NQ + q) * 4);
        if ((m4.x | m4.y | m4.z | m4.w) != 0) vbits |= 1u << c;
    }
    const int cnt = __popc(vbits);

    // softmax over this head's 32 logits (lane <-> logit lvl*8+pt)
    float aw[NLVL];
    {
        float v = g_attw[(size_t)q * 256 + h * 32 + lane];
        float m = v;
#pragma unroll
        for (int o = 16; o; o >>= 1) m = fmaxf(m, __shfl_xor_sync(0xffffffffu, m, o));
        float e = __expf(v - m);
        float s = e;
#pragma unroll
        for (int o = 16; o; o >>= 1) s += __shfl_xor_sync(0xffffffffu, s, o);
        float sm = e / s;
#pragma unroll
        for (int lvl = 0; lvl < NLVL; lvl++)
            aw[lvl] = __shfl_sync(0xffffffffu, sm, lvl * 8 + pL);
    }

    float ox[NLVL], oy[NLVL];   // -0.5 already folded in by the GEMM epilogue
    {
        const float* offq = g_off + (size_t)q * 512 + h * 64;
#pragma unroll
        for (int lvl = 0; lvl < NLVL; lvl++) {
            float2 o = *reinterpret_cast<const float2*>(offq + lvl * 16 + pL * 2);
            ox[lvl] = o.x; oy[lvl] = o.y;
        }
    }

    const uint32_t hb = (uint32_t)h * (SUMHW * DH);

    __half2 hacc[8];
#pragma unroll
    for (int j = 0; j < 8; j++) hacc[j] = __float2half2_rn(0.f);

#pragma unroll
    for (int c = 0; c < NCAM; c++) {
        if (!((vbits >> c) & 1u)) continue;
        float2 r2 = *reinterpret_cast<const float2*>(
            ref + ((size_t)c * NQ + q) * 8 + dd * 2);
        const float rx = r2.x, ry = r2.y;
        const uint8_t* vbc = g_vb8 + ((uint32_t)c * (NHEAD * SUMHW * DH) + hb);

#pragma unroll
        for (int lvl = 0; lvl < NLVL; lvl++) {
            const int wdim = 64 >> lvl;
            const uint32_t lbase = (lvl == 0) ? 0u : (lvl == 1) ? 131072u
                                 : (lvl == 2) ? 163840u : 172032u;  // LSTART*32
            const float wf = (float)wdim;
            const float wc = (float)(wdim - 2);
            float x = fmaf(rx, wf, ox[lvl]);
            float y = fmaf(ry, wf, oy[lvl]);
            float bxf = floorf(fminf(fmaxf(x, 0.f), wc));
            float byf = floorf(fminf(fmaxf(y, 0.f), wc));
            float fx  = fmaxf(0.f, 1.f - fabsf(x - (bxf + xcf))) * aw[lvl];
            float gy0 = fmaxf(0.f, 1.f - fabsf(y - byf));
            float gy1 = fmaxf(0.f, 1.f - fabsf(y - (byf + 1.f)));
            __half2 wA = __float2half2_rn(gy0 * fx);
            __half2 wB = __float2half2_rn(gy1 * fx);

            int idx = __float2int_rn(fmaf(byf, wf, bxf));
            uint32_t base = lbase + (uint32_t)idx * 32u + lsub;
            uint4 vA = __ldg(reinterpret_cast<const uint4*>(vbc + base));
            uint4 vB = __ldg(reinterpret_cast<const uint4*>(vbc + base + (uint32_t)wdim * 32u));

#define ACCUM16(WH, RAW)                                                          \
            {                                                                     \
                const uint32_t w32[4] = {(RAW).x, (RAW).y, (RAW).z, (RAW).w};     \
                _Pragma("unroll")                                                 \
                for (int wv = 0; wv < 4; wv++) {                                  \
                    uint16_t plo = (uint16_t)(w32[wv] & 0xFFFFu);                 \
                    uint16_t phi = (uint16_t)(w32[wv] >> 16);                     \
                    __half2_raw hlo = __nv_cvt_fp8x2_to_halfraw2(                 \
                        (__nv_fp8x2_storage_t)plo, __NV_E4M3);                    \
                    __half2_raw hhi = __nv_cvt_fp8x2_to_halfraw2(                 \
                        (__nv_fp8x2_storage_t)phi, __NV_E4M3);                    \
                    hacc[wv * 2 + 0] = __hfma2(WH, *reinterpret_cast<__half2*>(&hlo), hacc[wv * 2 + 0]); \
                    hacc[wv * 2 + 1] = __hfma2(WH, *reinterpret_cast<__half2*>(&hhi), hacc[wv * 2 + 1]); \
                }                                                                 \
            }
            ACCUM16(wA, vA)
            ACCUM16(wB, vB)
#undef ACCUM16
        }
    }

    // reduce over lanes sharing a channel group: bits 0 (x-corner), 2,3,4 (points)
#pragma unroll
    for (int s = 0; s < 4; s++) {
        const int off = (s == 0) ? 1 : (1 << (s + 1));
#pragma unroll
        for (int i = 0; i < 8; i++) {
            uint32_t u = *reinterpret_cast<uint32_t*>(&hacc[i]);
            uint32_t v = __shfl_xor_sync(0xffffffffu, u, off);
            hacc[i] = __hadd2(hacc[i], *reinterpret_cast<__half2*>(&v));
        }
    }

    if ((lane & 29) == 0) {   // lanes 0 and 2: channel halves 0 / 1
        const float inv = 0.0625f / (float)max(cnt, 1);  // undo x16 fp8 scale + mean
        float f[16];
#pragma unroll
        for (int j = 0; j < 8; j++) {
            float2 p = __half22float2(hacc[j]);
            f[2 * j]     = p.x * inv;
            f[2 * j + 1] = p.y * inv;
        }
        uint4 pk0, pk1;
        __nv_bfloat162 b0 = __floats2bfloat162_rn(f[0],  f[1]);
        __nv_bfloat162 b1 = __floats2bfloat162_rn(f[2],  f[3]);
        __nv_bfloat162 b2 = __floats2bfloat162_rn(f[4],  f[5]);
        __nv_bfloat162 b3 = __floats2bfloat162_rn(f[6],  f[7]);
        __nv_bfloat162 b4 = __floats2bfloat162_rn(f[8],  f[9]);
        __nv_bfloat162 b5 = __floats2bfloat162_rn(f[10], f[11]);
        __nv_bfloat162 b6 = __floats2bfloat162_rn(f[12], f[13]);
        __nv_bfloat162 b7 = __floats2bfloat162_rn(f[14], f[15]);
        pk0.x = *reinterpret_cast<uint32_t*>(&b0);
        pk0.y = *reinterpret_cast<uint32_t*>(&b1);
        pk0.z = *reinterpret_cast<uint32_t*>(&b2);
        pk0.w = *reinterpret_cast<uint32_t*>(&b3);
        pk1.x = *reinterpret_cast<uint32_t*>(&b4);
        pk1.y = *reinterpret_cast<uint32_t*>(&b5);
        pk1.z = *reinterpret_cast<uint32_t*>(&b6);
        pk1.w = *reinterpret_cast<uint32_t*>(&b7);
        __nv_bfloat16* dst = g_slots_bf + (size_t)q * DIMS + h * DH + (lane >> 1) * 16;
        *reinterpret_cast<uint4*>(dst)     = pk0;
        *reinterpret_cast<uint4*>(dst + 8) = pk1;
    }
}

// ---------------- launcher --------------------------------------------------------
extern "C" void kernel_launch(void* const* d_in, const int* in_sizes, int n_in,
                              void* d_out, int out_size)
{
    const float* query   = (const float*)d_in[0];
    const float* value   = (const float*)d_in[2];
    const float* refp    = (const float*)d_in[3];
    const int*   mask    = (const int*)  d_in[4];
    const float* value_W = (const float*)d_in[7];
    const float* value_b = (const float*)d_in[8];
    const float* off_W   = (const float*)d_in[9];
    const float* off_b   = (const float*)d_in[10];
    const float* attw_W  = (const float*)d_in[11];
    const float* attw_b  = (const float*)d_in[12];
    const float* out_W   = (const float*)d_in[13];
    const float* out_b   = (const float*)d_in[14];

    __nv_bfloat16* p_slots_bf;
    cudaGetSymbolAddress((void**)&p_slots_bf, g_slots_bf);

    // [0] all weight transposes + bias packing
    wtrans_all_kernel<<<dim3(16, 8, 4), 256>>>(
        value_W, off_W, attw_W, out_W, off_b, attw_b);

    // [1] fused pre-GEMM: vproj (fp8 head-major) + offsets/logits, 64x128/k32
    gemm_pre_kernel<<<1962, 256>>>(value, query, value_b);

    // [2] fused softmax + sampling + camera mean
    sample_fused_kernel<<<NQ, 256>>>(refp, mask);

    // [3] output projection + bias + residual (64x64/k32, resid prefetch)
    gemm_out_kernel<<<dim3(157, 4), 256>>>(p_slots_bf, out_b, query, (float*)d_out, NQ);
}